// round 11
// baseline (speedup 1.0000x reference)
#include <cuda_runtime.h>
#include <cstdint>

#define NTHREADS 256
#define BT 32
#define LSCALE 0.17677669529663687f  // 1/sqrt(32)

// ---------------- packed-weight device buffer (floats) ----------------
#define PK_W1   0        // KS=10 NTW=2 -> 5120
#define PK_WQ   5120     // KS=8  NTW=4 -> 8192
#define PK_W2   13312    // KS=8  NTW=2 -> 4096
#define PK_W3S  17408    // KS=8  NTW=2 -> 4096
#define PK_W3O  21504    // KS=16 NTW=2 -> 8192
#define PK_WK   29696    // KS=16 NTW=4 -> 16384
#define PK_WV   46080    // KS=16 NTW=4 -> 16384
#define PK_WE   62464    // 7 * 11264 = 78848
#define PK_TOTAL 141312
__device__ float g_pk[PK_TOTAL];

// ---------------- smem layout (floats) ----------------
// Activations in fragment-packed (APK) layout:
//   word(wm, ks, g, t, e) = (wm*KSMAX + ks)*128 + g*16 + t*4 + e
//   e = (row_in_16 >= 8 ? 1:0) + (k_in_8 >= 4 ? 2:0)
#define IN_KSMAX   11
#define ACT2_KSMAX 16
#define X1_KSMAX   8
#define OFF_WVPK 0        // Wv packed resident (16384)
#define OFF_IN   16384    // APK [2][11][128] = 2816
#define OFF_ACT2 19200    // APK [2][16][128] = 4096
#define OFF_X1   23296    // APK [2][8][128]  = 2048
#define OFF_BIA  25344    // 320
#define OFF_RED  25664    // 128
#define SMEM_FLOATS 25792 // 103168 bytes -> 2 CTAs/SM

__device__ __forceinline__ float tf32f(float x){
    uint32_t u; asm("cvt.rna.tf32.f32 %0, %1;" : "=r"(u) : "f"(x));
    return __uint_as_float(u);
}

// ================= prep kernel: pack weights fragment-major =================
#define PACK_REGION(DST, KS, NTW, KACT, SRCEXPR) do {                      \
    int SZ_ = (KS)*4*2*32*(NTW);                                           \
    for (int i_ = t0; i_ < SZ_; i_ += NT){                                 \
        int tile = i_ % (NTW); int r_ = i_ / (NTW);                        \
        int lane_ = r_ & 31; r_ >>= 5;                                     \
        int half_ = r_ & 1;  r_ >>= 1;                                     \
        int nw_ = r_ & 3;    int ks_ = r_ >> 2;                            \
        int k = ks_*8 + (lane_ & 3) + half_*4;                             \
        int n = nw_*8*(NTW) + tile*8 + (lane_ >> 2);                       \
        float v_ = 0.f;                                                    \
        if (k < (KACT)) { v_ = (SRCEXPR); }                                \
        (DST)[i_] = tf32f(v_);                                             \
    } } while(0)

__global__ void prep_kernel(const float* __restrict__ W1, const float* __restrict__ Wq,
                            const float* __restrict__ W2, const float* __restrict__ w3s,
                            const float* __restrict__ w3o, const float* __restrict__ Wk,
                            const float* __restrict__ Wv, const float* __restrict__ We){
    int t0 = blockIdx.x*blockDim.x + threadIdx.x;
    int NT = gridDim.x*blockDim.x;
    PACK_REGION(g_pk+PK_W1, 10, 2, 78, W1[k*64+n]);
    PACK_REGION(g_pk+PK_WQ,  8, 4, 64, Wq[(n>>5)*2048 + k*32 + (n&31)]);
    PACK_REGION(g_pk+PK_W2,  8, 2, 64, W2[k*64+n]);
    PACK_REGION(g_pk+PK_W3S, 8, 2, 64, w3s[k*64+n]);
    PACK_REGION(g_pk+PK_W3O,16, 2,128, w3o[k*64+n]);
    PACK_REGION(g_pk+PK_WK, 16, 4,128, Wk[(n>>5)*4096 + k*32 + (n&31)]);
    PACK_REGION(g_pk+PK_WV, 16, 4,128, Wv[(n>>5)*4096 + k*32 + (n&31)]);
    for (int a = 0; a < 7; a++){
        PACK_REGION(g_pk+PK_WE + a*11264, 11, 4, 82, We[a*82*128 + k*128 + n]);
    }
}

// ================= main kernel helpers =================
__device__ __forceinline__ void cp_async16(float* dst, const float* src){
    uint32_t s = (uint32_t)__cvta_generic_to_shared(dst);
    asm volatile("cp.async.cg.shared.global [%0], [%1], 16;" :: "r"(s), "l"(src));
}
__device__ __forceinline__ void cp_commit(){
    asm volatile("cp.async.commit_group;");
}
__device__ __forceinline__ void cp_wait0(){
    asm volatile("cp.async.wait_group 0;" ::: "memory");
}

__device__ __forceinline__ void mma8(float* c, const uint32_t* a, uint32_t b0, uint32_t b1){
    asm volatile("mma.sync.aligned.m16n8k8.row.col.f32.tf32.tf32.f32 "
        "{%0,%1,%2,%3},{%4,%5,%6,%7},{%8,%9},{%0,%1,%2,%3};"
        : "+f"(c[0]),"+f"(c[1]),"+f"(c[2]),"+f"(c[3])
        : "r"(a[0]),"r"(a[1]),"r"(a[2]),"r"(a[3]),"r"(b0),"r"(b1));
}

// A from APK smem (one LDS.128 per ks), B packed (L2 if BG else smem)
template<int KSMAX, int KS, int NTW, bool BG>
__device__ __forceinline__ void run_mma_pk(const float* __restrict__ Apk,
                                           const float* __restrict__ Bpk,
                                           float (&C)[NTW][4],
                                           int warp_m, int warp_n, int g, int t, int lane)
{
#pragma unroll
    for (int nt=0;nt<NTW;nt++)
#pragma unroll
        for (int j=0;j<4;j++) C[nt][j]=0.f;
    const float* ap = Apk + warp_m*KSMAX*128 + g*16 + t*4;
#pragma unroll
    for (int ks=0; ks<KS; ks++){
        float4 av = *reinterpret_cast<const float4*>(ap + ks*128);
        uint32_t a[4] = {__float_as_uint(av.x), __float_as_uint(av.y),
                         __float_as_uint(av.z), __float_as_uint(av.w)};
        const float* bp = Bpk + ((size_t)((ks*4 + warp_n)*2)*32 + lane)*NTW;
        uint32_t b0[NTW], b1[NTW];
        if constexpr (NTW==4){
            float4 x, y;
            if constexpr (BG){
                x = __ldg(reinterpret_cast<const float4*>(bp));
                y = __ldg(reinterpret_cast<const float4*>(bp + 32*4));
            } else {
                x = *reinterpret_cast<const float4*>(bp);
                y = *reinterpret_cast<const float4*>(bp + 32*4);
            }
            b0[0]=__float_as_uint(x.x); b0[1]=__float_as_uint(x.y);
            b0[2]=__float_as_uint(x.z); b0[3]=__float_as_uint(x.w);
            b1[0]=__float_as_uint(y.x); b1[1]=__float_as_uint(y.y);
            b1[2]=__float_as_uint(y.z); b1[3]=__float_as_uint(y.w);
        } else {
            float2 x, y;
            if constexpr (BG){
                x = __ldg(reinterpret_cast<const float2*>(bp));
                y = __ldg(reinterpret_cast<const float2*>(bp + 32*2));
            } else {
                x = *reinterpret_cast<const float2*>(bp);
                y = *reinterpret_cast<const float2*>(bp + 32*2);
            }
            b0[0]=__float_as_uint(x.x); b0[1]=__float_as_uint(x.y);
            b1[0]=__float_as_uint(y.x); b1[1]=__float_as_uint(y.y);
        }
#pragma unroll
        for (int nt=0;nt<NTW;nt++)
            mma8(C[nt], a, b0[nt], b1[nt]);
    }
}

// C-frags -> APK layout (two STS.64 per nt)
template<int KSMAX, int NTW, bool RELU, bool BIAS, bool CVT>
__device__ __forceinline__ void epi_store_pk(float (&C)[NTW][4], float* __restrict__ Opk,
                                             const float* __restrict__ bias,
                                             int warp_m, int warp_n, int g, int t)
{
#pragma unroll
    for (int nt=0;nt<NTW;nt++){
        int col = warp_n*(8*NTW) + nt*8 + 2*t;
        int ks2 = col >> 3, kin = col & 7;
        int w0 = (warp_m*KSMAX + ks2)*128 + g*16 + (kin&3)*4 + ((kin>>2)<<1);
        float bb0 = BIAS ? bias[col]   : 0.f;
        float bb1 = BIAS ? bias[col+1] : 0.f;
        float v0 = C[nt][0]+bb0, v1 = C[nt][1]+bb1;
        float v2 = C[nt][2]+bb0, v3 = C[nt][3]+bb1;
        if (RELU){ v0=fmaxf(v0,0.f); v1=fmaxf(v1,0.f); v2=fmaxf(v2,0.f); v3=fmaxf(v3,0.f); }
        if (CVT){ v0=tf32f(v0); v1=tf32f(v1); v2=tf32f(v2); v3=tf32f(v3); }
        *reinterpret_cast<float2*>(Opk + w0)     = make_float2(v0, v2);  // k=col, rows r0/r0+8
        *reinterpret_cast<float2*>(Opk + w0 + 4) = make_float2(v1, v3);  // k=col+1
    }
}

// stage global rows into APK layout (4 scattered STS.32 per float4)
__device__ __forceinline__ void stage_row_pk(float* dst, int ksmax, int row, int c, float4 v){
    int wm = row >> 4, rin = row & 15, gg = rin & 7, rb = rin >> 3;
    int ks2 = c >> 3, half = (c & 7) >> 2;
    float* base = dst + (wm*ksmax + ks2)*128 + gg*16 + half*2 + rb;
    base[0]  = v.x;
    base[4]  = v.y;
    base[8]  = v.z;
    base[12] = v.w;
}

__device__ __forceinline__ void stage_agent(float* IN, const float* __restrict__ so,
                                            const float* __restrict__ ao,
                                            int B, int b0, int a, int tid){
    for (int i = tid; i < BT*22; i += NTHREADS){
        int row = i/22, c4 = i - row*22; int c = c4*4;
        float4 v;
        if (c4 < 16){
            v = *reinterpret_cast<const float4*>(so + ((size_t)a*B + b0+row)*64 + c);
        } else {
            const float* ap = ao + ((size_t)a*B + b0+row)*18;
            int j = c - 64;
            v.x = (j   < 18) ? ap[j]   : 0.f;
            v.y = (j+1 < 18) ? ap[j+1] : 0.f;
            v.z = (j+2 < 18) ? ap[j+2] : 0.f;
            v.w = (j+3 < 18) ? ap[j+3] : 0.f;
        }
        v.x=tf32f(v.x); v.y=tf32f(v.y); v.z=tf32f(v.z); v.w=tf32f(v.w);
        stage_row_pk(IN, IN_KSMAX, row, c, v);
    }
}

__global__ void __launch_bounds__(NTHREADS,2) ac_kernel(
    const float* __restrict__ state_one, const float* __restrict__ act_one,
    const float* __restrict__ state_others, const float* __restrict__ act_others,
    const float* __restrict__ b1, const float* __restrict__ b2,
    const float* __restrict__ be, const float* __restrict__ bv,
    const float* __restrict__ Wout, const float* __restrict__ bout,
    float* __restrict__ out, int B)
{
    extern __shared__ float sm[];
    float* WVPK = sm + OFF_WVPK;
    float* IN   = sm + OFF_IN;
    float* ACT2 = sm + OFF_ACT2;
    float* X1   = sm + OFF_X1;
    float* BIA  = sm + OFF_BIA;
    float* RED  = sm + OFF_RED;

    const int tid = threadIdx.x;
    const int lane = tid & 31;
    const int warp = tid >> 5;
    const int g = lane >> 2, t = lane & 3;
    const int warp_m = warp & 1, warp_n = warp >> 1;
    const int b0 = blockIdx.x * BT;

    // ---- initial staging: Wv via cp.async; self inputs + biases ----
    for (int i = tid*4; i < 16384; i += NTHREADS*4) cp_async16(WVPK+i, g_pk+PK_WV+i);
    cp_commit();
    for (int i = tid; i < BT*20; i += NTHREADS){
        int row = i/20, c4 = i - row*20; int c = c4*4;
        float4 v;
        if (c4 < 16){
            v = *reinterpret_cast<const float4*>(state_one + (size_t)(b0+row)*64 + c);
        } else {
            const float* ap = act_one + (size_t)(b0+row)*14;
            int j = c - 64;
            v.x = (j   < 14) ? ap[j]   : 0.f;
            v.y = (j+1 < 14) ? ap[j+1] : 0.f;
            v.z = (j+2 < 14) ? ap[j+2] : 0.f;
            v.w = (j+3 < 14) ? ap[j+3] : 0.f;
        }
        v.x=tf32f(v.x); v.y=tf32f(v.y); v.z=tf32f(v.z); v.w=tf32f(v.w);
        stage_row_pk(IN, IN_KSMAX, row, c, v);
    }
    for (int i = tid; i < 320; i += NTHREADS){
        float v;
        if (i < 64) v = b1[i];
        else if (i < 128) v = b2[i-64];
        else if (i < 256) v = bv[i-128];
        else v = Wout[i-256];
        BIA[i] = v;
    }
    __syncthreads();                                           // #1

    // S1: x1 = relu(x @ W1 + b1) -> X1 APK
    {
        float C[2][4];
        run_mma_pk<IN_KSMAX,10,2,true>(IN, g_pk+PK_W1, C, warp_m, warp_n, g, t, lane);
        epi_store_pk<X1_KSMAX,2,true,true,true>(C, X1, BIA, warp_m, warp_n, g, t);
    }
    __syncthreads();                                           // #2

    // S4: sel = x1 @ Wq_all -> fragment registers (pre-scaled)
    float sf[4][4];
    {
        float C[4][4];
        run_mma_pk<X1_KSMAX,8,4,true>(X1, g_pk+PK_WQ, C, warp_m, warp_n, g, t, lane);
#pragma unroll
        for (int nt=0;nt<4;nt++)
#pragma unroll
            for (int j=0;j<4;j++) sf[nt][j] = C[nt][j]*LSCALE;
    }
    // S2: x2 = relu(x1 @ W2 + b2) -> ACT2 APK
    {
        float C[2][4];
        run_mma_pk<X1_KSMAX,8,2,true>(X1, g_pk+PK_W2, C, warp_m, warp_n, g, t, lane);
        epi_store_pk<ACT2_KSMAX,2,true,true,true>(C, ACT2, BIA+64, warp_m, warp_n, g, t);
    }
    __syncthreads();                                           // #3

    // S3: x3_self = x2 @ w3_self -> registers
    float x3s[2][4];
    run_mma_pk<ACT2_KSMAX,8,2,true>(ACT2, g_pk+PK_W3S, x3s, warp_m, warp_n, g, t, lane);
    // stage agent-0 inputs
    stage_agent(IN, state_others, act_others, B, b0, 0, tid);
    cp_wait0();
    __syncthreads();                                           // #4

    // register softmax state + ov accumulators
    float m0 = -1e30f, m1 = -1e30f, s0 = 0.f, s1 = 0.f;
    float ov[4][4];
#pragma unroll
    for (int nt=0;nt<4;nt++)
#pragma unroll
        for (int j=0;j<4;j++) ov[nt][j]=0.f;

    // ---- agent loop: 2 syncs/iter, merged keys+vals MMA ----
    for (int a = 0; a < 7; a++){
        // enc = relu(inp @ We[a] + be[a]) -> ACT2 APK (We B-frags from L2)
        {
            float C[4][4];
            run_mma_pk<IN_KSMAX,11,4,true>(IN, g_pk+PK_WE + a*11264, C, warp_m, warp_n, g, t, lane);
            epi_store_pk<ACT2_KSMAX,4,true,true,true>(C, ACT2, be + a*128, warp_m, warp_n, g, t);
        }
        __syncthreads();

        if (a < 6) stage_agent(IN, state_others, act_others, B, b0, a+1, tid);

        // merged keys+vals: one pass over enc A-frags
        float Ck[4][4], Cv[4][4];
#pragma unroll
        for (int nt=0;nt<4;nt++)
#pragma unroll
            for (int j=0;j<4;j++){ Ck[nt][j]=0.f; Cv[nt][j]=0.f; }
        {
            const float* ap = ACT2 + warp_m*ACT2_KSMAX*128 + g*16 + t*4;
#pragma unroll
            for (int ks=0; ks<16; ks++){
                float4 av = *reinterpret_cast<const float4*>(ap + ks*128);
                uint32_t aa[4] = {__float_as_uint(av.x), __float_as_uint(av.y),
                                  __float_as_uint(av.z), __float_as_uint(av.w)};
                const float* bk = g_pk + PK_WK + ((size_t)((ks*4 + warp_n)*2)*32 + lane)*4;
                const float* bw = WVPK + ((size_t)((ks*4 + warp_n)*2)*32 + lane)*4;
                float4 xk = __ldg(reinterpret_cast<const float4*>(bk));
                float4 yk = __ldg(reinterpret_cast<const float4*>(bk + 128));
                float4 xv = *reinterpret_cast<const float4*>(bw);
                float4 yv = *reinterpret_cast<const float4*>(bw + 128);
                uint32_t kb0[4] = {__float_as_uint(xk.x),__float_as_uint(xk.y),
                                   __float_as_uint(xk.z),__float_as_uint(xk.w)};
                uint32_t kb1[4] = {__float_as_uint(yk.x),__float_as_uint(yk.y),
                                   __float_as_uint(yk.z),__float_as_uint(yk.w)};
                uint32_t vb0[4] = {__float_as_uint(xv.x),__float_as_uint(xv.y),
                                   __float_as_uint(xv.z),__float_as_uint(xv.w)};
                uint32_t vb1[4] = {__float_as_uint(yv.x),__float_as_uint(yv.y),
                                   __float_as_uint(yv.z),__float_as_uint(yv.w)};
#pragma unroll
                for (int nt=0;nt<4;nt++){
                    mma8(Ck[nt], aa, kb0[nt], kb1[nt]);
                    mma8(Cv[nt], aa, vb0[nt], vb1[nt]);
                }
            }
        }
        // fragment logits -> register softmax
        float lg0, lg1;
        {
            float p0 = 0.f, p1 = 0.f;
#pragma unroll
            for (int nt=0;nt<4;nt++){
                p0 += Ck[nt][0]*sf[nt][0] + Ck[nt][1]*sf[nt][1];
                p1 += Ck[nt][2]*sf[nt][2] + Ck[nt][3]*sf[nt][3];
            }
            p0 += __shfl_xor_sync(0xffffffffu, p0, 1);
            p0 += __shfl_xor_sync(0xffffffffu, p0, 2);
            p1 += __shfl_xor_sync(0xffffffffu, p1, 1);
            p1 += __shfl_xor_sync(0xffffffffu, p1, 2);
            lg0 = p0; lg1 = p1;
        }
        float mn0 = fmaxf(m0, lg0), mn1 = fmaxf(m1, lg1);
        float al0 = __expf(m0 - mn0), al1 = __expf(m1 - mn1);
        float pv0 = __expf(lg0 - mn0), pv1 = __expf(lg1 - mn1);
        s0 = s0*al0 + pv0; s1 = s1*al1 + pv1;
        m0 = mn0; m1 = mn1;

        // vals epilogue + ov update
#pragma unroll
        for (int nt=0;nt<4;nt++){
            int col = warp_n*32 + nt*8 + 2*t;
            float bv0 = BIA[128+col], bv1 = BIA[128+col+1];
            float v0 = fmaxf(Cv[nt][0]+bv0, 0.f);
            float v1 = fmaxf(Cv[nt][1]+bv1, 0.f);
            float v2 = fmaxf(Cv[nt][2]+bv0, 0.f);
            float v3 = fmaxf(Cv[nt][3]+bv1, 0.f);
            ov[nt][0] = ov[nt][0]*al0 + pv0*v0;
            ov[nt][1] = ov[nt][1]*al0 + pv0*v1;
            ov[nt][2] = ov[nt][2]*al1 + pv1*v2;
            ov[nt][3] = ov[nt][3]*al1 + pv1*v3;
        }
        __syncthreads();
    }

    // x2_others = ov / s -> ACT2 APK (fragment-local)
    {
        float i0 = 1.f / s0, i1 = 1.f / s1;
#pragma unroll
        for (int nt=0;nt<4;nt++){
            int col = warp_n*32 + nt*8 + 2*t;
            int ks2 = col >> 3, kin = col & 7;
            int w0 = (warp_m*ACT2_KSMAX + ks2)*128 + g*16 + (kin&3)*4 + ((kin>>2)<<1);
            *reinterpret_cast<float2*>(ACT2 + w0) =
                make_float2(tf32f(ov[nt][0]*i0), tf32f(ov[nt][2]*i1));
            *reinterpret_cast<float2*>(ACT2 + w0 + 4) =
                make_float2(tf32f(ov[nt][1]*i0), tf32f(ov[nt][3]*i1));
        }
    }
    __syncthreads();

    // S8: x3o = x2o @ w3_others; x3 = relu(x3_self + x3o); dot Wout
    {
        float C[2][4];
        run_mma_pk<ACT2_KSMAX,16,2,true>(ACT2, g_pk+PK_W3O, C, warp_m, warp_n, g, t, lane);
        int r0 = warp_m*16 + g;
        float pr0 = 0.f, pr1 = 0.f;
#pragma unroll
        for (int nt=0;nt<2;nt++){
            int col = warp_n*16 + nt*8 + 2*t;
            float w0 = BIA[256+col], w1 = BIA[256+col+1];
            pr0 += fmaxf(C[nt][0]+x3s[nt][0], 0.f)*w0 + fmaxf(C[nt][1]+x3s[nt][1], 0.f)*w1;
            pr1 += fmaxf(C[nt][2]+x3s[nt][2], 0.f)*w0 + fmaxf(C[nt][3]+x3s[nt][3], 0.f)*w1;
        }
        pr0 += __shfl_xor_sync(0xffffffffu, pr0, 1);
        pr1 += __shfl_xor_sync(0xffffffffu, pr1, 1);
        pr0 += __shfl_xor_sync(0xffffffffu, pr0, 2);
        pr1 += __shfl_xor_sync(0xffffffffu, pr1, 2);
        if (t == 0){
            RED[warp_n*32 + r0]     = pr0;
            RED[warp_n*32 + r0 + 8] = pr1;
        }
    }
    __syncthreads();
    if (tid < 32){
        out[b0 + tid] = RED[tid] + RED[32+tid] + RED[64+tid] + RED[96+tid] + bout[0];
    }
}

extern "C" void kernel_launch(void* const* d_in, const int* in_sizes, int n_in,
                              void* d_out, int out_size)
{
    const float* state_one    = (const float*)d_in[0];
    const float* act_one      = (const float*)d_in[1];
    const float* state_others = (const float*)d_in[2];
    const float* act_others   = (const float*)d_in[3];
    const float* W1   = (const float*)d_in[4];
    const float* b1   = (const float*)d_in[5];
    const float* W2   = (const float*)d_in[6];
    const float* b2   = (const float*)d_in[7];
    const float* w3s  = (const float*)d_in[8];
    const float* We   = (const float*)d_in[9];
    const float* be   = (const float*)d_in[10];
    const float* Wk   = (const float*)d_in[11];
    const float* Wq   = (const float*)d_in[12];
    const float* Wv   = (const float*)d_in[13];
    const float* bv   = (const float*)d_in[14];
    const float* w3o  = (const float*)d_in[15];
    const float* Wout = (const float*)d_in[16];
    const float* bout = (const float*)d_in[17];
    float* out = (float*)d_out;

    int B = in_sizes[0] / 64;

    prep_kernel<<<138, 256>>>(W1, Wq, W2, w3s, w3o, Wk, Wv, We);

    int smem_bytes = SMEM_FLOATS * sizeof(float);
    cudaFuncSetAttribute(ac_kernel, cudaFuncAttributeMaxDynamicSharedMemorySize, smem_bytes);
    ac_kernel<<<B/BT, NTHREADS, smem_bytes>>>(
        state_one, act_one, state_others, act_others,
        b1, b2, be, bv, Wout, bout, out, B);
}

// round 12
// speedup vs baseline: 1.3121x; 1.3121x over previous
#include <cuda_runtime.h>
#include <cstdint>

#define NTHREADS 256
#define BT 32
#define LSCALE 0.17677669529663687f  // 1/sqrt(32)
#define INSTR 92

// ---------------- packed-weight device buffer (floats) ----------------
#define PK_W1   0        // KS=10 NTW=2 -> 5120
#define PK_WQ   5120     // KS=8  NTW=4 -> 8192
#define PK_W2   13312    // KS=8  NTW=2 -> 4096
#define PK_W3S  17408    // KS=8  NTW=2 -> 4096
#define PK_W3O  21504    // KS=16 NTW=2 -> 8192
#define PK_WK   29696    // KS=16 NTW=4 -> 16384
#define PK_WV   46080    // KS=16 NTW=4 -> 16384
#define PK_WE   62464    // 7 * 11264 = 78848
#define PK_TOTAL 141312
__device__ float g_pk[PK_TOTAL];

// ---------------- smem layout (floats) ----------------
#define OFF_IN0  0        // [32][92] = 2944 (agent inputs, even agents + self)
#define OFF_IN1  2944     // [32][92] = 2944 (odd agents; X1 aliases in prologue)
#define OFF_A20  5888     // [32][132] = 4224 (enc double buffer 0)
#define OFF_A21  10112    // [32][132] = 4224 (enc double buffer 1)
#define OFF_BIA  14336    // 320
#define OFF_RED  14656    // 128
#define SMEM_FLOATS 14784 // 59136 bytes -> 2 CTAs/SM easily

__device__ __forceinline__ float tf32f(float x){
    uint32_t u; asm("cvt.rna.tf32.f32 %0, %1;" : "=r"(u) : "f"(x));
    return __uint_as_float(u);
}

// ================= prep kernel: pack weights fragment-major =================
#define PACK_REGION(DST, KS, NTW, KACT, SRCEXPR) do {                      \
    int SZ_ = (KS)*4*2*32*(NTW);                                           \
    for (int i_ = t0; i_ < SZ_; i_ += NT){                                 \
        int tile = i_ % (NTW); int r_ = i_ / (NTW);                        \
        int lane_ = r_ & 31; r_ >>= 5;                                     \
        int half_ = r_ & 1;  r_ >>= 1;                                     \
        int nw_ = r_ & 3;    int ks_ = r_ >> 2;                            \
        int k = ks_*8 + (lane_ & 3) + half_*4;                             \
        int n = nw_*8*(NTW) + tile*8 + (lane_ >> 2);                       \
        float v_ = 0.f;                                                    \
        if (k < (KACT)) { v_ = (SRCEXPR); }                                \
        (DST)[i_] = tf32f(v_);                                             \
    } } while(0)

__global__ void prep_kernel(const float* __restrict__ W1, const float* __restrict__ Wq,
                            const float* __restrict__ W2, const float* __restrict__ w3s,
                            const float* __restrict__ w3o, const float* __restrict__ Wk,
                            const float* __restrict__ Wv, const float* __restrict__ We){
    int t0 = blockIdx.x*blockDim.x + threadIdx.x;
    int NT = gridDim.x*blockDim.x;
    PACK_REGION(g_pk+PK_W1, 10, 2, 78, W1[k*64+n]);
    PACK_REGION(g_pk+PK_WQ,  8, 4, 64, Wq[(n>>5)*2048 + k*32 + (n&31)]);
    PACK_REGION(g_pk+PK_W2,  8, 2, 64, W2[k*64+n]);
    PACK_REGION(g_pk+PK_W3S, 8, 2, 64, w3s[k*64+n]);
    PACK_REGION(g_pk+PK_W3O,16, 2,128, w3o[k*64+n]);
    PACK_REGION(g_pk+PK_WK, 16, 4,128, Wk[(n>>5)*4096 + k*32 + (n&31)]);
    PACK_REGION(g_pk+PK_WV, 16, 4,128, Wv[(n>>5)*4096 + k*32 + (n&31)]);
    for (int a = 0; a < 7; a++){
        PACK_REGION(g_pk+PK_WE + a*11264, 11, 4, 82, We[a*82*128 + k*128 + n]);
    }
}

// ================= main kernel helpers =================
__device__ __forceinline__ void mma8(float* c, const uint32_t* a, uint32_t b0, uint32_t b1){
    asm volatile("mma.sync.aligned.m16n8k8.row.col.f32.tf32.tf32.f32 "
        "{%0,%1,%2,%3},{%4,%5,%6,%7},{%8,%9},{%0,%1,%2,%3};"
        : "+f"(c[0]),"+f"(c[1]),"+f"(c[2]),"+f"(c[3])
        : "r"(a[0]),"r"(a[1]),"r"(a[2]),"r"(a[3]),"r"(b0),"r"(b1));
}

// warp tile: 16 rows (warp_m 0..1) x 8*NTW cols (warp_n 0..3); B always from L2 packed
template<int KS, int NTW>
__device__ __forceinline__ void run_mma(const float* __restrict__ A, int astr,
                                        const float* __restrict__ Bpk,
                                        float (&C)[NTW][4],
                                        int warp_m, int warp_n, int g, int t, int lane)
{
#pragma unroll
    for (int nt=0;nt<NTW;nt++)
#pragma unroll
        for (int j=0;j<4;j++) C[nt][j]=0.f;
    const float* ap = A + (warp_m*16 + g)*astr + t;
#pragma unroll
    for (int ks=0; ks<KS; ks++){
        uint32_t a[4];
        a[0] = __float_as_uint(ap[ks*8]);
        a[1] = __float_as_uint(ap[8*astr + ks*8]);
        a[2] = __float_as_uint(ap[ks*8 + 4]);
        a[3] = __float_as_uint(ap[8*astr + ks*8 + 4]);
        const float* bp = Bpk + ((size_t)((ks*4 + warp_n)*2)*32 + lane)*NTW;
        uint32_t b0[NTW], b1[NTW];
        if constexpr (NTW==4){
            float4 x = __ldg(reinterpret_cast<const float4*>(bp));
            float4 y = __ldg(reinterpret_cast<const float4*>(bp + 32*4));
            b0[0]=__float_as_uint(x.x); b0[1]=__float_as_uint(x.y);
            b0[2]=__float_as_uint(x.z); b0[3]=__float_as_uint(x.w);
            b1[0]=__float_as_uint(y.x); b1[1]=__float_as_uint(y.y);
            b1[2]=__float_as_uint(y.z); b1[3]=__float_as_uint(y.w);
        } else {
            float2 x = __ldg(reinterpret_cast<const float2*>(bp));
            float2 y = __ldg(reinterpret_cast<const float2*>(bp + 32*2));
            b0[0]=__float_as_uint(x.x); b0[1]=__float_as_uint(x.y);
            b1[0]=__float_as_uint(y.x); b1[1]=__float_as_uint(y.y);
        }
#pragma unroll
        for (int nt=0;nt<NTW;nt++)
            mma8(C[nt], a, b0[nt], b1[nt]);
    }
}

template<int NTW, bool RELU, bool BIAS, bool CVT>
__device__ __forceinline__ void epi_store(float (&C)[NTW][4], float* __restrict__ O, int ostr,
                                          const float* __restrict__ bias,
                                          int warp_m, int warp_n, int g, int t)
{
    int r0 = warp_m*16 + g;
#pragma unroll
    for (int nt=0;nt<NTW;nt++){
        int col = warp_n*(8*NTW) + nt*8 + 2*t;
        float bb0 = BIAS ? bias[col]   : 0.f;
        float bb1 = BIAS ? bias[col+1] : 0.f;
        float v0 = C[nt][0]+bb0, v1 = C[nt][1]+bb1;
        float v2 = C[nt][2]+bb0, v3 = C[nt][3]+bb1;
        if (RELU){ v0=fmaxf(v0,0.f); v1=fmaxf(v1,0.f); v2=fmaxf(v2,0.f); v3=fmaxf(v3,0.f); }
        if (CVT){ v0=tf32f(v0); v1=tf32f(v1); v2=tf32f(v2); v3=tf32f(v3); }
        *reinterpret_cast<float2*>(O + r0*ostr + col)     = make_float2(v0,v1);
        *reinterpret_cast<float2*>(O + (r0+8)*ostr + col) = make_float2(v2,v3);
    }
}

__device__ __forceinline__ void stage_agent(float* IN, const float* __restrict__ so,
                                            const float* __restrict__ ao,
                                            int B, int b0, int a, int tid){
    for (int i = tid; i < BT*22; i += NTHREADS){
        int row = i/22, c4 = i - row*22; int c = c4*4;
        float4 v;
        if (c4 < 16){
            v = *reinterpret_cast<const float4*>(so + ((size_t)a*B + b0+row)*64 + c);
        } else {
            const float* ap = ao + ((size_t)a*B + b0+row)*18;
            int j = c - 64;
            v.x = (j   < 18) ? ap[j]   : 0.f;
            v.y = (j+1 < 18) ? ap[j+1] : 0.f;
            v.z = (j+2 < 18) ? ap[j+2] : 0.f;
            v.w = (j+3 < 18) ? ap[j+3] : 0.f;
        }
        v.x=tf32f(v.x); v.y=tf32f(v.y); v.z=tf32f(v.z); v.w=tf32f(v.w);
        *reinterpret_cast<float4*>(IN + row*INSTR + c) = v;
    }
}

__global__ void __launch_bounds__(NTHREADS,2) ac_kernel(
    const float* __restrict__ state_one, const float* __restrict__ act_one,
    const float* __restrict__ state_others, const float* __restrict__ act_others,
    const float* __restrict__ b1, const float* __restrict__ b2,
    const float* __restrict__ be, const float* __restrict__ bv,
    const float* __restrict__ Wout, const float* __restrict__ bout,
    float* __restrict__ out, int B)
{
    extern __shared__ float sm[];
    float* IN[2]   = { sm + OFF_IN0, sm + OFF_IN1 };
    float* ACT2[2] = { sm + OFF_A20, sm + OFF_A21 };
    float* X1   = sm + OFF_IN1;   // alias: X1 lifetime ends before IN1 first written
    float* BIA  = sm + OFF_BIA;
    float* RED  = sm + OFF_RED;

    const int tid = threadIdx.x;
    const int lane = tid & 31;
    const int warp = tid >> 5;
    const int g = lane >> 2, t = lane & 3;
    const int warp_m = warp & 1, warp_n = warp >> 1;
    const int b0 = blockIdx.x * BT;

    // ---- stage self inputs -> IN0; biases ----
    for (int i = tid; i < BT*20; i += NTHREADS){
        int row = i/20, c4 = i - row*20; int c = c4*4;
        float4 v;
        if (c4 < 16){
            v = *reinterpret_cast<const float4*>(state_one + (size_t)(b0+row)*64 + c);
        } else {
            const float* ap = act_one + (size_t)(b0+row)*14;
            int j = c - 64;
            v.x = (j   < 14) ? ap[j]   : 0.f;
            v.y = (j+1 < 14) ? ap[j+1] : 0.f;
            v.z = (j+2 < 14) ? ap[j+2] : 0.f;
            v.w = (j+3 < 14) ? ap[j+3] : 0.f;
        }
        v.x=tf32f(v.x); v.y=tf32f(v.y); v.z=tf32f(v.z); v.w=tf32f(v.w);
        *reinterpret_cast<float4*>(IN[0] + row*INSTR + c) = v;
    }
    for (int i = tid; i < 320; i += NTHREADS){
        float v;
        if (i < 64) v = b1[i];
        else if (i < 128) v = b2[i-64];
        else if (i < 256) v = bv[i-128];
        else v = Wout[i-256];
        BIA[i] = v;
    }
    __syncthreads();

    // S1: x1 = relu(x @ W1 + b1) -> X1 (aliases IN1; safe, IN1 unused yet)
    {
        float C[2][4];
        run_mma<10,2>(IN[0], INSTR, g_pk+PK_W1, C, warp_m, warp_n, g, t, lane);
        epi_store<2,true,true,true>(C, X1, 68, BIA, warp_m, warp_n, g, t);
    }
    __syncthreads();

    // S4: sel = x1 @ Wq_all -> fragment registers (pre-scaled)
    float sf[4][4];
    {
        float C[4][4];
        run_mma<8,4>(X1, 68, g_pk+PK_WQ, C, warp_m, warp_n, g, t, lane);
#pragma unroll
        for (int nt=0;nt<4;nt++)
#pragma unroll
            for (int j=0;j<4;j++) sf[nt][j] = C[nt][j]*LSCALE;
    }
    // S2: x2 = relu(x1 @ W2 + b2) -> ACT2[0]
    {
        float C[2][4];
        run_mma<8,2>(X1, 68, g_pk+PK_W2, C, warp_m, warp_n, g, t, lane);
        epi_store<2,true,true,true>(C, ACT2[0], 132, BIA+64, warp_m, warp_n, g, t);
    }
    __syncthreads();

    // S3: x3_self = x2 @ w3_self -> registers
    float x3s[2][4];
    run_mma<8,2>(ACT2[0], 132, g_pk+PK_W3S, x3s, warp_m, warp_n, g, t, lane);
    // stage agent-0 inputs -> IN0 (self-input reads finished at previous sync)
    stage_agent(IN[0], state_others, act_others, B, b0, 0, tid);
    __syncthreads();

    // register softmax state + ov accumulators
    float m0 = -1e30f, m1 = -1e30f, s0 = 0.f, s1 = 0.f;
    float ov[4][4];
#pragma unroll
    for (int nt=0;nt<4;nt++)
#pragma unroll
        for (int j=0;j<4;j++) ov[nt][j]=0.f;

    // ---- software-pipelined agent loop: 8 iterations, ONE sync each ----
    // iter i: attention on enc[i-1] (ACT2[(i-1)&1]) ∥ enc of agent i (-> ACT2[i&1])
    for (int i = 0; i < 8; i++){
        if (i > 0){
            const float* encb = ACT2[(i-1)&1];
            // keys MMA -> fragment logits -> register softmax
            float lg0, lg1;
            {
                float Ck[4][4];
                run_mma<16,4>(encb, 132, g_pk+PK_WK, Ck, warp_m, warp_n, g, t, lane);
                float p0 = 0.f, p1 = 0.f;
#pragma unroll
                for (int nt=0;nt<4;nt++){
                    p0 += Ck[nt][0]*sf[nt][0] + Ck[nt][1]*sf[nt][1];
                    p1 += Ck[nt][2]*sf[nt][2] + Ck[nt][3]*sf[nt][3];
                }
                p0 += __shfl_xor_sync(0xffffffffu, p0, 1);
                p0 += __shfl_xor_sync(0xffffffffu, p0, 2);
                p1 += __shfl_xor_sync(0xffffffffu, p1, 1);
                p1 += __shfl_xor_sync(0xffffffffu, p1, 2);
                lg0 = p0; lg1 = p1;
            }
            float mn0 = fmaxf(m0, lg0), mn1 = fmaxf(m1, lg1);
            float al0 = __expf(m0 - mn0), al1 = __expf(m1 - mn1);
            float pv0 = __expf(lg0 - mn0), pv1 = __expf(lg1 - mn1);
            s0 = s0*al0 + pv0; s1 = s1*al1 + pv1;
            m0 = mn0; m1 = mn1;
            // vals MMA (Wv from L2) + local epilogue into ov
            {
                float Cv[4][4];
                run_mma<16,4>(encb, 132, g_pk+PK_WV, Cv, warp_m, warp_n, g, t, lane);
#pragma unroll
                for (int nt=0;nt<4;nt++){
                    int col = warp_n*32 + nt*8 + 2*t;
                    float bv0 = BIA[128+col], bv1 = BIA[128+col+1];
                    float v0 = fmaxf(Cv[nt][0]+bv0, 0.f);
                    float v1 = fmaxf(Cv[nt][1]+bv1, 0.f);
                    float v2 = fmaxf(Cv[nt][2]+bv0, 0.f);
                    float v3 = fmaxf(Cv[nt][3]+bv1, 0.f);
                    ov[nt][0] = ov[nt][0]*al0 + pv0*v0;
                    ov[nt][1] = ov[nt][1]*al0 + pv0*v1;
                    ov[nt][2] = ov[nt][2]*al1 + pv1*v2;
                    ov[nt][3] = ov[nt][3]*al1 + pv1*v3;
                }
            }
        }
        if (i < 7){
            // enc = relu(inp @ We[i] + be[i]) -> ACT2[i&1]
            float C[4][4];
            run_mma<11,4>(IN[i&1], INSTR, g_pk+PK_WE + i*11264, C, warp_m, warp_n, g, t, lane);
            epi_store<4,true,true,true>(C, ACT2[i&1], 132, be + i*128, warp_m, warp_n, g, t);
        }
        if (i < 6) stage_agent(IN[(i+1)&1], state_others, act_others, B, b0, i+1, tid);
        __syncthreads();
    }

    // x2_others = ov / s -> ACT2[0] (tf32), fragment-local
    {
        int r0 = warp_m*16 + g, r1 = r0 + 8;
        float i0 = 1.f / s0, i1 = 1.f / s1;
#pragma unroll
        for (int nt=0;nt<4;nt++){
            int col = warp_n*32 + nt*8 + 2*t;
            *reinterpret_cast<float2*>(ACT2[0] + r0*132 + col) =
                make_float2(tf32f(ov[nt][0]*i0), tf32f(ov[nt][1]*i0));
            *reinterpret_cast<float2*>(ACT2[0] + r1*132 + col) =
                make_float2(tf32f(ov[nt][2]*i1), tf32f(ov[nt][3]*i1));
        }
    }
    __syncthreads();

    // S8: x3o = x2o @ w3_others; x3 = relu(x3_self + x3o); dot Wout
    {
        float C[2][4];
        run_mma<16,2>(ACT2[0], 132, g_pk+PK_W3O, C, warp_m, warp_n, g, t, lane);
        int r0 = warp_m*16 + g;
        float pr0 = 0.f, pr1 = 0.f;
#pragma unroll
        for (int nt=0;nt<2;nt++){
            int col = warp_n*16 + nt*8 + 2*t;
            float w0 = BIA[256+col], w1 = BIA[256+col+1];
            pr0 += fmaxf(C[nt][0]+x3s[nt][0], 0.f)*w0 + fmaxf(C[nt][1]+x3s[nt][1], 0.f)*w1;
            pr1 += fmaxf(C[nt][2]+x3s[nt][2], 0.f)*w0 + fmaxf(C[nt][3]+x3s[nt][3], 0.f)*w1;
        }
        pr0 += __shfl_xor_sync(0xffffffffu, pr0, 1);
        pr1 += __shfl_xor_sync(0xffffffffu, pr1, 1);
        pr0 += __shfl_xor_sync(0xffffffffu, pr0, 2);
        pr1 += __shfl_xor_sync(0xffffffffu, pr1, 2);
        if (t == 0){
            RED[warp_n*32 + r0]     = pr0;
            RED[warp_n*32 + r0 + 8] = pr1;
        }
    }
    __syncthreads();
    if (tid < 32){
        out[b0 + tid] = RED[tid] + RED[32+tid] + RED[64+tid] + RED[96+tid] + bout[0];
    }
}

extern "C" void kernel_launch(void* const* d_in, const int* in_sizes, int n_in,
                              void* d_out, int out_size)
{
    const float* state_one    = (const float*)d_in[0];
    const float* act_one      = (const float*)d_in[1];
    const float* state_others = (const float*)d_in[2];
    const float* act_others   = (const float*)d_in[3];
    const float* W1   = (const float*)d_in[4];
    const float* b1   = (const float*)d_in[5];
    const float* W2   = (const float*)d_in[6];
    const float* b2   = (const float*)d_in[7];
    const float* w3s  = (const float*)d_in[8];
    const float* We   = (const float*)d_in[9];
    const float* be   = (const float*)d_in[10];
    const float* Wk   = (const float*)d_in[11];
    const float* Wq   = (const float*)d_in[12];
    const float* Wv   = (const float*)d_in[13];
    const float* bv   = (const float*)d_in[14];
    const float* w3o  = (const float*)d_in[15];
    const float* Wout = (const float*)d_in[16];
    const float* bout = (const float*)d_in[17];
    float* out = (float*)d_out;

    int B = in_sizes[0] / 64;

    prep_kernel<<<138, 256>>>(W1, Wq, W2, w3s, w3o, Wk, Wv, We);

    int smem_bytes = SMEM_FLOATS * sizeof(float);
    cudaFuncSetAttribute(ac_kernel, cudaFuncAttributeMaxDynamicSharedMemorySize, smem_bytes);
    ac_kernel<<<B/BT, NTHREADS, smem_bytes>>>(
        state_one, act_one, state_others, act_others,
        b1, b2, be, bv, Wout, bout, out, B);
}

// round 14
// speedup vs baseline: 1.5024x; 1.1450x over previous
#include <cuda_runtime.h>
#include <cstdint>

#define NTHREADS 256
#define BT 32
#define LSCALE 0.17677669529663687f  // 1/sqrt(32)
#define INSTR 92

// ---------------- packed-weight device buffer (floats) ----------------
#define PK_W1   0        // KS=10 NTW=2 -> 5120
#define PK_WQ   5120     // KS=8  NTW=4 -> 8192
#define PK_W2   13312    // KS=8  NTW=2 -> 4096
#define PK_W3S  17408    // KS=8  NTW=2 -> 4096
#define PK_W3O  21504    // KS=16 NTW=2 -> 8192
#define PK_WK   29696    // KS=16 NTW=4 -> 16384
#define PK_WV   46080    // KS=16 NTW=4 -> 16384
#define PK_WE   62464    // 7 * 11264 = 78848
#define PK_TOTAL 141312
__device__ float g_pk[PK_TOTAL];

// ---------------- smem layout (floats) ----------------
#define OFF_WVPK 0        // Wv packed resident (16384)
#define OFF_IN   16384    // [32][92] inputs (2944)
#define OFF_ACT2 19328    // [32][132] sel-temp/x2/enc/x2_others (4224)
#define OFF_X1   23552    // [32][68] x1 (2176)
#define OFF_BIA  25728    // 320
#define OFF_RED  26048    // 128
#define SMEM_FLOATS 26176 // 104704 bytes -> 2 CTAs/SM

// half-block barrier: 4 warps (128 threads) of row-half m use barrier id 1+m
#define BAR_HALF(idreg) asm volatile("bar.sync %0, 128;" :: "r"(idreg) : "memory")

__device__ __forceinline__ float tf32f(float x){
    uint32_t u; asm("cvt.rna.tf32.f32 %0, %1;" : "=r"(u) : "f"(x));
    return __uint_as_float(u);
}

// ================= prep kernel: pack weights fragment-major =================
#define PACK_REGION(DST, KS, NTW, KACT, SRCEXPR) do {                      \
    int SZ_ = (KS)*4*2*32*(NTW);                                           \
    for (int i_ = t0; i_ < SZ_; i_ += NT){                                 \
        int tile = i_ % (NTW); int r_ = i_ / (NTW);                        \
        int lane_ = r_ & 31; r_ >>= 5;                                     \
        int half_ = r_ & 1;  r_ >>= 1;                                     \
        int nw_ = r_ & 3;    int ks_ = r_ >> 2;                            \
        int k = ks_*8 + (lane_ & 3) + half_*4;                             \
        int n = nw_*8*(NTW) + tile*8 + (lane_ >> 2);                       \
        float v_ = 0.f;                                                    \
        if (k < (KACT)) { v_ = (SRCEXPR); }                                \
        (DST)[i_] = tf32f(v_);                                             \
    } } while(0)

__global__ void prep_kernel(const float* __restrict__ W1, const float* __restrict__ Wq,
                            const float* __restrict__ W2, const float* __restrict__ w3s,
                            const float* __restrict__ w3o, const float* __restrict__ Wk,
                            const float* __restrict__ Wv, const float* __restrict__ We){
    int t0 = blockIdx.x*blockDim.x + threadIdx.x;
    int NT = gridDim.x*blockDim.x;
    PACK_REGION(g_pk+PK_W1, 10, 2, 78, W1[k*64+n]);
    PACK_REGION(g_pk+PK_WQ,  8, 4, 64, Wq[(n>>5)*2048 + k*32 + (n&31)]);
    PACK_REGION(g_pk+PK_W2,  8, 2, 64, W2[k*64+n]);
    PACK_REGION(g_pk+PK_W3S, 8, 2, 64, w3s[k*64+n]);
    PACK_REGION(g_pk+PK_W3O,16, 2,128, w3o[k*64+n]);
    PACK_REGION(g_pk+PK_WK, 16, 4,128, Wk[(n>>5)*4096 + k*32 + (n&31)]);
    PACK_REGION(g_pk+PK_WV, 16, 4,128, Wv[(n>>5)*4096 + k*32 + (n&31)]);
    for (int a = 0; a < 7; a++){
        PACK_REGION(g_pk+PK_WE + a*11264, 11, 4, 82, We[a*82*128 + k*128 + n]);
    }
}

// ================= main kernel helpers =================
__device__ __forceinline__ void cp_async16(float* dst, const float* src){
    uint32_t s = (uint32_t)__cvta_generic_to_shared(dst);
    asm volatile("cp.async.cg.shared.global [%0], [%1], 16;" :: "r"(s), "l"(src));
}
__device__ __forceinline__ void cp_commit(){
    asm volatile("cp.async.commit_group;");
}
__device__ __forceinline__ void cp_wait0(){
    asm volatile("cp.async.wait_group 0;" ::: "memory");
}

__device__ __forceinline__ void mma8(float* c, const uint32_t* a, uint32_t b0, uint32_t b1){
    asm volatile("mma.sync.aligned.m16n8k8.row.col.f32.tf32.tf32.f32 "
        "{%0,%1,%2,%3},{%4,%5,%6,%7},{%8,%9},{%0,%1,%2,%3};"
        : "+f"(c[0]),"+f"(c[1]),"+f"(c[2]),"+f"(c[3])
        : "r"(a[0]),"r"(a[1]),"r"(a[2]),"r"(a[3]),"r"(b0),"r"(b1));
}

// warp tile: 16 rows (warp_m 0..1) x 8*NTW cols (warp_n 0..3); BG=1 -> B from L2
template<int KS, int NTW, bool BG>
__device__ __forceinline__ void run_mma(const float* __restrict__ A, int astr,
                                        const float* __restrict__ Bpk,
                                        float (&C)[NTW][4],
                                        int warp_m, int warp_n, int g, int t, int lane)
{
#pragma unroll
    for (int nt=0;nt<NTW;nt++)
#pragma unroll
        for (int j=0;j<4;j++) C[nt][j]=0.f;
    const float* ap = A + (warp_m*16 + g)*astr + t;
#pragma unroll
    for (int ks=0; ks<KS; ks++){
        uint32_t a[4];
        a[0] = __float_as_uint(ap[ks*8]);
        a[1] = __float_as_uint(ap[8*astr + ks*8]);
        a[2] = __float_as_uint(ap[ks*8 + 4]);
        a[3] = __float_as_uint(ap[8*astr + ks*8 + 4]);
        const float* bp = Bpk + ((size_t)((ks*4 + warp_n)*2)*32 + lane)*NTW;
        uint32_t b0[NTW], b1[NTW];
        if constexpr (NTW==4){
            float4 x, y;
            if constexpr (BG){
                x = __ldg(reinterpret_cast<const float4*>(bp));
                y = __ldg(reinterpret_cast<const float4*>(bp + 32*4));
            } else {
                x = *reinterpret_cast<const float4*>(bp);
                y = *reinterpret_cast<const float4*>(bp + 32*4);
            }
            b0[0]=__float_as_uint(x.x); b0[1]=__float_as_uint(x.y);
            b0[2]=__float_as_uint(x.z); b0[3]=__float_as_uint(x.w);
            b1[0]=__float_as_uint(y.x); b1[1]=__float_as_uint(y.y);
            b1[2]=__float_as_uint(y.z); b1[3]=__float_as_uint(y.w);
        } else {
            float2 x, y;
            if constexpr (BG){
                x = __ldg(reinterpret_cast<const float2*>(bp));
                y = __ldg(reinterpret_cast<const float2*>(bp + 32*2));
            } else {
                x = *reinterpret_cast<const float2*>(bp);
                y = *reinterpret_cast<const float2*>(bp + 32*2);
            }
            b0[0]=__float_as_uint(x.x); b0[1]=__float_as_uint(x.y);
            b1[0]=__float_as_uint(y.x); b1[1]=__float_as_uint(y.y);
        }
#pragma unroll
        for (int nt=0;nt<NTW;nt++)
            mma8(C[nt], a, b0[nt], b1[nt]);
    }
}

template<int NTW, bool RELU, bool BIAS, bool CVT>
__device__ __forceinline__ void epi_store(float (&C)[NTW][4], float* __restrict__ O, int ostr,
                                          const float* __restrict__ bias,
                                          int warp_m, int warp_n, int g, int t)
{
    int r0 = warp_m*16 + g;
#pragma unroll
    for (int nt=0;nt<NTW;nt++){
        int col = warp_n*(8*NTW) + nt*8 + 2*t;
        float bb0 = BIAS ? bias[col]   : 0.f;
        float bb1 = BIAS ? bias[col+1] : 0.f;
        float v0 = C[nt][0]+bb0, v1 = C[nt][1]+bb1;
        float v2 = C[nt][2]+bb0, v3 = C[nt][3]+bb1;
        if (RELU){ v0=fmaxf(v0,0.f); v1=fmaxf(v1,0.f); v2=fmaxf(v2,0.f); v3=fmaxf(v3,0.f); }
        if (CVT){ v0=tf32f(v0); v1=tf32f(v1); v2=tf32f(v2); v3=tf32f(v3); }
        *reinterpret_cast<float2*>(O + r0*ostr + col)     = make_float2(v0,v1);
        *reinterpret_cast<float2*>(O + (r0+8)*ostr + col) = make_float2(v2,v3);
    }
}

// per-half staging: half m stages its 16 rows with its 128 threads
__device__ __forceinline__ void stage_agent_half(float* IN, const float* __restrict__ so,
                                                 const float* __restrict__ ao,
                                                 int B, int b0, int a, int half, int tid_h){
    for (int i = tid_h; i < 16*22; i += 128){
        int row = half*16 + i/22, c4 = i % 22; int c = c4*4;
        float4 v;
        if (c4 < 16){
            v = *reinterpret_cast<const float4*>(so + ((size_t)a*B + b0+row)*64 + c);
        } else {
            const float* ap = ao + ((size_t)a*B + b0+row)*18;
            int j = c - 64;
            v.x = (j   < 18) ? ap[j]   : 0.f;
            v.y = (j+1 < 18) ? ap[j+1] : 0.f;
            v.z = (j+2 < 18) ? ap[j+2] : 0.f;
            v.w = (j+3 < 18) ? ap[j+3] : 0.f;
        }
        v.x=tf32f(v.x); v.y=tf32f(v.y); v.z=tf32f(v.z); v.w=tf32f(v.w);
        *reinterpret_cast<float4*>(IN + row*INSTR + c) = v;
    }
}

__global__ void __launch_bounds__(NTHREADS,2) ac_kernel(
    const float* __restrict__ state_one, const float* __restrict__ act_one,
    const float* __restrict__ state_others, const float* __restrict__ act_others,
    const float* __restrict__ b1, const float* __restrict__ b2,
    const float* __restrict__ be, const float* __restrict__ bv,
    const float* __restrict__ Wout, const float* __restrict__ bout,
    float* __restrict__ out, int B)
{
    extern __shared__ float sm[];
    float* WVPK = sm + OFF_WVPK;
    float* IN   = sm + OFF_IN;
    float* ACT2 = sm + OFF_ACT2;
    float* X1   = sm + OFF_X1;
    float* BIA  = sm + OFF_BIA;
    float* RED  = sm + OFF_RED;

    const int tid = threadIdx.x;
    const int lane = tid & 31;
    const int warp = tid >> 5;
    const int g = lane >> 2, t = lane & 3;
    const int warp_m = warp & 1, warp_n = warp >> 1;
    const int b0 = blockIdx.x * BT;
    const int barid = 1 + warp_m;                 // named barrier id for this half
    const int tid_h = ((warp >> 1) << 5) + lane;  // 0..127 within the half

    // ---- initial staging: Wv via cp.async; self inputs + biases ----
    for (int i = tid*4; i < 16384; i += NTHREADS*4) cp_async16(WVPK+i, g_pk+PK_WV+i);
    cp_commit();
    for (int i = tid; i < BT*20; i += NTHREADS){
        int row = i/20, c4 = i - row*20; int c = c4*4;
        float4 v;
        if (c4 < 16){
            v = *reinterpret_cast<const float4*>(state_one + (size_t)(b0+row)*64 + c);
        } else {
            const float* ap = act_one + (size_t)(b0+row)*14;
            int j = c - 64;
            v.x = (j   < 14) ? ap[j]   : 0.f;
            v.y = (j+1 < 14) ? ap[j+1] : 0.f;
            v.z = (j+2 < 14) ? ap[j+2] : 0.f;
            v.w = (j+3 < 14) ? ap[j+3] : 0.f;
        }
        v.x=tf32f(v.x); v.y=tf32f(v.y); v.z=tf32f(v.z); v.w=tf32f(v.w);
        *reinterpret_cast<float4*>(IN + row*INSTR + c) = v;
    }
    for (int i = tid; i < 320; i += NTHREADS){
        float v;
        if (i < 64) v = b1[i];
        else if (i < 128) v = b2[i-64];
        else if (i < 256) v = bv[i-128];
        else v = Wout[i-256];
        BIA[i] = v;
    }
    __syncthreads();                                           // #1 (block)

    // S1: x1 = relu(x @ W1 + b1) -> X1 (B from L2)
    {
        float C[2][4];
        run_mma<10,2,true>(IN, INSTR, g_pk+PK_W1, C, warp_m, warp_n, g, t, lane);
        epi_store<2,true,true,true>(C, X1, 68, BIA, warp_m, warp_n, g, t);
    }
    BAR_HALF(barid);   // X1 rows of this half fully written by this half

    // S4: sel = x1 @ Wq_all -> fragment registers (pre-scaled)
    float sf[4][4];
    {
        float C[4][4];
        run_mma<8,4,true>(X1, 68, g_pk+PK_WQ, C, warp_m, warp_n, g, t, lane);
#pragma unroll
        for (int nt=0;nt<4;nt++)
#pragma unroll
            for (int j=0;j<4;j++) sf[nt][j] = C[nt][j]*LSCALE;
    }
    // S2: x2 = relu(x1 @ W2 + b2) -> ACT2
    {
        float C[2][4];
        run_mma<8,2,true>(X1, 68, g_pk+PK_W2, C, warp_m, warp_n, g, t, lane);
        epi_store<2,true,true,true>(C, ACT2, 132, BIA+64, warp_m, warp_n, g, t);
    }
    BAR_HALF(barid);

    // S3: x3_self = x2 @ w3_self -> registers
    float x3s[2][4];
    run_mma<8,2,true>(ACT2, 132, g_pk+PK_W3S, x3s, warp_m, warp_n, g, t, lane);
    // stage agent-0 inputs for this half (self-input reads of this half done)
    stage_agent_half(IN, state_others, act_others, B, b0, 0, warp_m, tid_h);
    cp_wait0();            // Wv resident complete (block-wide data, read-only after)
    __syncthreads();       // #2 (block) — ensures WVPK visible to all

    // register softmax state + ov accumulators
    float m0 = -1e30f, m1 = -1e30f, s0 = 0.f, s1 = 0.f;
    float ov[4][4];
#pragma unroll
    for (int nt=0;nt<4;nt++)
#pragma unroll
        for (int j=0;j<4;j++) ov[nt][j]=0.f;

    // ---- agent loop: 2 HALF barriers per iteration (4-warp scope) ----
    for (int a = 0; a < 7; a++){
        // enc = relu(inp @ We[a] + be[a]) -> ACT2 rows of this half
        {
            float C[4][4];
            run_mma<11,4,true>(IN, INSTR, g_pk+PK_WE + a*11264, C, warp_m, warp_n, g, t, lane);
            epi_store<4,true,true,true>(C, ACT2, 132, be + a*128, warp_m, warp_n, g, t);
        }
        BAR_HALF(barid);

        // stage next agent inputs for this half (overlaps keys/vals below)
        if (a < 6) stage_agent_half(IN, state_others, act_others, B, b0, a+1, warp_m, tid_h);

        // keys MMA (Wk from L2) -> fragment logits -> register softmax
        float lg0, lg1;
        {
            float Ck[4][4];
            run_mma<16,4,true>(ACT2, 132, g_pk+PK_WK, Ck, warp_m, warp_n, g, t, lane);
            float p0 = 0.f, p1 = 0.f;
#pragma unroll
            for (int nt=0;nt<4;nt++){
                p0 += Ck[nt][0]*sf[nt][0] + Ck[nt][1]*sf[nt][1];
                p1 += Ck[nt][2]*sf[nt][2] + Ck[nt][3]*sf[nt][3];
            }
            p0 += __shfl_xor_sync(0xffffffffu, p0, 1);
            p0 += __shfl_xor_sync(0xffffffffu, p0, 2);
            p1 += __shfl_xor_sync(0xffffffffu, p1, 1);
            p1 += __shfl_xor_sync(0xffffffffu, p1, 2);
            lg0 = p0; lg1 = p1;
        }
        float mn0 = fmaxf(m0, lg0), mn1 = fmaxf(m1, lg1);
        float al0 = __expf(m0 - mn0), al1 = __expf(m1 - mn1);
        float pv0 = __expf(lg0 - mn0), pv1 = __expf(lg1 - mn1);
        s0 = s0*al0 + pv0; s1 = s1*al1 + pv1;
        m0 = mn0; m1 = mn1;

        // vals MMA (B = resident Wv in smem) + local epilogue into ov
        {
            float Cv[4][4];
            run_mma<16,4,false>(ACT2, 132, WVPK, Cv, warp_m, warp_n, g, t, lane);
#pragma unroll
            for (int nt=0;nt<4;nt++){
                int col = warp_n*32 + nt*8 + 2*t;
                float bv0 = BIA[128+col], bv1 = BIA[128+col+1];
                float v0 = fmaxf(Cv[nt][0]+bv0, 0.f);
                float v1 = fmaxf(Cv[nt][1]+bv1, 0.f);
                float v2 = fmaxf(Cv[nt][2]+bv0, 0.f);
                float v3 = fmaxf(Cv[nt][3]+bv1, 0.f);
                ov[nt][0] = ov[nt][0]*al0 + pv0*v0;
                ov[nt][1] = ov[nt][1]*al0 + pv0*v1;
                ov[nt][2] = ov[nt][2]*al1 + pv1*v2;
                ov[nt][3] = ov[nt][3]*al1 + pv1*v3;
            }
        }
        BAR_HALF(barid);
    }

    // x2_others = ov / s -> ACT2 (tf32), fragment-local (half-local rows)
    {
        int r0 = warp_m*16 + g, r1 = r0 + 8;
        float i0 = 1.f / s0, i1 = 1.f / s1;
#pragma unroll
        for (int nt=0;nt<4;nt++){
            int col = warp_n*32 + nt*8 + 2*t;
            *reinterpret_cast<float2*>(ACT2 + r0*132 + col) =
                make_float2(tf32f(ov[nt][0]*i0), tf32f(ov[nt][1]*i0));
            *reinterpret_cast<float2*>(ACT2 + r1*132 + col) =
                make_float2(tf32f(ov[nt][2]*i1), tf32f(ov[nt][3]*i1));
        }
    }
    BAR_HALF(barid);

    // S8: x3o = x2o @ w3_others; x3 = relu(x3_self + x3o); dot Wout
    {
        float C[2][4];
        run_mma<16,2,true>(ACT2, 132, g_pk+PK_W3O, C, warp_m, warp_n, g, t, lane);
        int r0 = warp_m*16 + g;
        float pr0 = 0.f, pr1 = 0.f;
#pragma unroll
        for (int nt=0;nt<2;nt++){
            int col = warp_n*16 + nt*8 + 2*t;
            float w0 = BIA[256+col], w1 = BIA[256+col+1];
            pr0 += fmaxf(C[nt][0]+x3s[nt][0], 0.f)*w0 + fmaxf(C[nt][1]+x3s[nt][1], 0.f)*w1;
            pr1 += fmaxf(C[nt][2]+x3s[nt][2], 0.f)*w0 + fmaxf(C[nt][3]+x3s[nt][3], 0.f)*w1;
        }
        pr0 += __shfl_xor_sync(0xffffffffu, pr0, 1);
        pr1 += __shfl_xor_sync(0xffffffffu, pr1, 1);
        pr0 += __shfl_xor_sync(0xffffffffu, pr0, 2);
        pr1 += __shfl_xor_sync(0xffffffffu, pr1, 2);
        if (t == 0){
            RED[warp_n*32 + r0]     = pr0;
            RED[warp_n*32 + r0 + 8] = pr1;
        }
    }
    __syncthreads();       // block: RED fully written before cross-half read
    if (tid < 32){
        out[b0 + tid] = RED[tid] + RED[32+tid] + RED[64+tid] + RED[96+tid] + bout[0];
    }
}

extern "C" void kernel_launch(void* const* d_in, const int* in_sizes, int n_in,
                              void* d_out, int out_size)
{
    const float* state_one    = (const float*)d_in[0];
    const float* act_one      = (const float*)d_in[1];
    const float* state_others = (const float*)d_in[2];
    const float* act_others   = (const float*)d_in[3];
    const float* W1   = (const float*)d_in[4];
    const float* b1   = (const float*)d_in[5];
    const float* W2   = (const float*)d_in[6];
    const float* b2   = (const float*)d_in[7];
    const float* w3s  = (const float*)d_in[8];
    const float* We   = (const float*)d_in[9];
    const float* be   = (const float*)d_in[10];
    const float* Wk   = (const float*)d_in[11];
    const float* Wq   = (const float*)d_in[12];
    const float* Wv   = (const float*)d_in[13];
    const float* bv   = (const float*)d_in[14];
    const float* w3o  = (const float*)d_in[15];
    const float* Wout = (const float*)d_in[16];
    const float* bout = (const float*)d_in[17];
    float* out = (float*)d_out;

    int B = in_sizes[0] / 64;

    prep_kernel<<<138, 256>>>(W1, Wq, W2, w3s, w3o, Wk, Wv, We);

    int smem_bytes = SMEM_FLOATS * sizeof(float);
    cudaFuncSetAttribute(ac_kernel, cudaFuncAttributeMaxDynamicSharedMemorySize, smem_bytes);
    ac_kernel<<<B/BT, NTHREADS, smem_bytes>>>(
        state_one, act_one, state_others, act_others,
        b1, b2, be, bv, Wout, bout, out, B);
}

// round 17
// speedup vs baseline: 2.2411x; 1.4916x over previous
#include <cuda_runtime.h>
#include <cstdint>

#define NTHREADS 256
#define BT 32
#define LSCALE 0.17677669529663687f  // 1/sqrt(32)

// activation smem strides (u32 units), ≡4 mod 32 for conflict-free frag loads
#define IN_STR 52
#define A2_STR 68
#define X1_STR 36

// ---------------- packed-weight device buffer (bf16x2 u32) ----------------
#define PK_W1   0        // KS=5  NTW=2 -> 2560
#define PK_WQ   2560     // KS=4  NTW=4 -> 4096
#define PK_W2   6656     // KS=4  NTW=2 -> 2048
#define PK_W3S  8704     // KS=4  NTW=2 -> 2048
#define PK_W3O  10752    // KS=8  NTW=2 -> 4096
#define PK_WK   14848    // KS=8  NTW=4 -> 8192
#define PK_WV   23040    // KS=8  NTW=4 -> 8192
#define PK_WE   31232    // 7 * 6144 = 43008
#define PK_TOTAL 74240
__device__ unsigned g_pk[PK_TOTAL];

// ---------------- smem layout (u32/float words) ----------------
#define OFF_WVPK 0        // Wv packed resident (8192)
#define OFF_IN   8192     // [32][52] u32 (1664)
#define OFF_ACT2 9856     // [32][68] u32 (2176)
#define OFF_X1   12032    // [32][36] u32 (1152)
#define OFF_BIA  13184    // 320 floats
#define OFF_RED  13504    // 128 floats
#define SMEM_WORDS 13632  // 54528 bytes -> 2 CTAs/SM

#define BAR_HALF(idreg) asm volatile("bar.sync %0, 128;" :: "r"(idreg) : "memory")

__device__ __forceinline__ unsigned bfpack(float lo, float hi){
    unsigned u; asm("cvt.rn.bf16x2.f32 %0, %1, %2;" : "=r"(u) : "f"(hi), "f"(lo));
    return u;
}

// ================= prep kernel: pack weights bf16 fragment-major =================
// dst[i], i = (((ks*4+nw)*2+half)*32+lane)*NTW + tile
// b0/b1 frag for m16n8k16: k0 = ks*16 + (lane&3)*2 + half*8 ; n = nw*8*NTW + tile*8 + lane/4
#define PACK_REGION(DST, KS, NTW, KACT, SRCEXPR) do {                      \
    int SZ_ = (KS)*4*2*32*(NTW);                                           \
    for (int i_ = t0; i_ < SZ_; i_ += NT){                                 \
        int tile = i_ % (NTW); int r_ = i_ / (NTW);                        \
        int lane_ = r_ & 31; r_ >>= 5;                                     \
        int half_ = r_ & 1;  r_ >>= 1;                                     \
        int nw_ = r_ & 3;    int ks_ = r_ >> 2;                            \
        int k0_ = ks_*16 + (lane_ & 3)*2 + half_*8;                        \
        int n = nw_*8*(NTW) + tile*8 + (lane_ >> 2);                       \
        float v0_ = 0.f, v1_ = 0.f;                                        \
        { int k = k0_;   if (k < (KACT)) v0_ = (SRCEXPR); }                \
        { int k = k0_+1; if (k < (KACT)) v1_ = (SRCEXPR); }                \
        (DST)[i_] = bfpack(v0_, v1_);                                      \
    } } while(0)

__global__ void prep_kernel(const float* __restrict__ W1, const float* __restrict__ Wq,
                            const float* __restrict__ W2, const float* __restrict__ w3s,
                            const float* __restrict__ w3o, const float* __restrict__ Wk,
                            const float* __restrict__ Wv, const float* __restrict__ We){
    int t0 = blockIdx.x*blockDim.x + threadIdx.x;
    int NT = gridDim.x*blockDim.x;
    PACK_REGION(g_pk+PK_W1,  5, 2, 78, W1[k*64+n]);
    PACK_REGION(g_pk+PK_WQ,  4, 4, 64, Wq[(n>>5)*2048 + k*32 + (n&31)]);
    PACK_REGION(g_pk+PK_W2,  4, 2, 64, W2[k*64+n]);
    PACK_REGION(g_pk+PK_W3S, 4, 2, 64, w3s[k*64+n]);
    PACK_REGION(g_pk+PK_W3O, 8, 2,128, w3o[k*64+n]);
    PACK_REGION(g_pk+PK_WK,  8, 4,128, Wk[(n>>5)*4096 + k*32 + (n&31)]);
    PACK_REGION(g_pk+PK_WV,  8, 4,128, Wv[(n>>5)*4096 + k*32 + (n&31)]);
    for (int a = 0; a < 7; a++){
        PACK_REGION(g_pk+PK_WE + a*6144, 6, 4, 82, We[a*82*128 + k*128 + n]);
    }
}

// ================= main kernel helpers =================
__device__ __forceinline__ void cp_async16(unsigned* dst, const unsigned* src){
    uint32_t s = (uint32_t)__cvta_generic_to_shared(dst);
    asm volatile("cp.async.cg.shared.global [%0], [%1], 16;" :: "r"(s), "l"(src));
}
__device__ __forceinline__ void cp_commit(){ asm volatile("cp.async.commit_group;"); }
__device__ __forceinline__ void cp_wait0(){ asm volatile("cp.async.wait_group 0;" ::: "memory"); }

__device__ __forceinline__ void mma16(float* c, const unsigned* a, unsigned b0, unsigned b1){
    asm volatile("mma.sync.aligned.m16n8k16.row.col.f32.bf16.bf16.f32 "
        "{%0,%1,%2,%3},{%4,%5,%6,%7},{%8,%9},{%0,%1,%2,%3};"
        : "+f"(c[0]),"+f"(c[1]),"+f"(c[2]),"+f"(c[3])
        : "r"(a[0]),"r"(a[1]),"r"(a[2]),"r"(a[3]),"r"(b0),"r"(b1));
}

// A: packed bf16x2 activations in smem (u32, astr stride); B: packed (L2 if BG else smem)
template<int KS, int NTW, bool BG>
__device__ __forceinline__ void run_mma(const unsigned* __restrict__ A, int astr,
                                        const unsigned* __restrict__ Bpk,
                                        float (&C)[NTW][4],
                                        int warp_m, int warp_n, int g, int t, int lane)
{
#pragma unroll
    for (int nt=0;nt<NTW;nt++)
#pragma unroll
        for (int j=0;j<4;j++) C[nt][j]=0.f;
    const unsigned* ap = A + (warp_m*16 + g)*astr + t;
#pragma unroll
    for (int ks=0; ks<KS; ks++){
        unsigned a[4];
        a[0] = ap[ks*8];
        a[1] = ap[8*astr + ks*8];
        a[2] = ap[ks*8 + 4];
        a[3] = ap[8*astr + ks*8 + 4];
        const unsigned* bp = Bpk + ((size_t)((ks*4 + warp_n)*2)*32 + lane)*NTW;
        unsigned b0[NTW], b1[NTW];
        if constexpr (NTW==4){
            uint4 x, y;
            if constexpr (BG){
                x = __ldg(reinterpret_cast<const uint4*>(bp));
                y = __ldg(reinterpret_cast<const uint4*>(bp + 32*4));
            } else {
                x = *reinterpret_cast<const uint4*>(bp);
                y = *reinterpret_cast<const uint4*>(bp + 32*4);
            }
            b0[0]=x.x; b0[1]=x.y; b0[2]=x.z; b0[3]=x.w;
            b1[0]=y.x; b1[1]=y.y; b1[2]=y.z; b1[3]=y.w;
        } else {
            uint2 x, y;
            if constexpr (BG){
                x = __ldg(reinterpret_cast<const uint2*>(bp));
                y = __ldg(reinterpret_cast<const uint2*>(bp + 32*2));
            } else {
                x = *reinterpret_cast<const uint2*>(bp);
                y = *reinterpret_cast<const uint2*>(bp + 32*2);
            }
            b0[0]=x.x; b0[1]=x.y;
            b1[0]=y.x; b1[1]=y.y;
        }
#pragma unroll
        for (int nt=0;nt<NTW;nt++)
            mma16(C[nt], a, b0[nt], b1[nt]);
    }
}

// C-frags (+bias, relu) -> packed bf16x2 smem
template<int NTW, bool RELU, bool BIAS>
__device__ __forceinline__ void epi_store(float (&C)[NTW][4], unsigned* __restrict__ O, int ostr,
                                          const float* __restrict__ bias,
                                          int warp_m, int warp_n, int g, int t)
{
    int r0 = warp_m*16 + g;
#pragma unroll
    for (int nt=0;nt<NTW;nt++){
        int col = warp_n*(8*NTW) + nt*8 + 2*t;
        int c2  = col >> 1;
        float bb0 = BIAS ? bias[col]   : 0.f;
        float bb1 = BIAS ? bias[col+1] : 0.f;
        float v0 = C[nt][0]+bb0, v1 = C[nt][1]+bb1;
        float v2 = C[nt][2]+bb0, v3 = C[nt][3]+bb1;
        if (RELU){ v0=fmaxf(v0,0.f); v1=fmaxf(v1,0.f); v2=fmaxf(v2,0.f); v3=fmaxf(v3,0.f); }
        O[r0*ostr + c2]     = bfpack(v0, v1);
        O[(r0+8)*ostr + c2] = bfpack(v2, v3);
    }
}

// per-half staging: 16 rows, 24 float4 per row (96 floats -> 48 u32; zero-padded)
__device__ __forceinline__ void stage_agent_half(unsigned* IN, const float* __restrict__ so,
                                                 const float* __restrict__ ao,
                                                 int B, int b0, int a, int half, int tid_h){
    for (int i = tid_h; i < 16*24; i += 128){
        int row = half*16 + i/24, c4 = i % 24; int c = c4*4;
        float4 v;
        if (c4 < 16){
            v = *reinterpret_cast<const float4*>(so + ((size_t)a*B + b0+row)*64 + c);
        } else {
            const float* ap = ao + ((size_t)a*B + b0+row)*18;
            int j = c - 64;
            v.x = (j   < 18) ? ap[j]   : 0.f;
            v.y = (j+1 < 18) ? ap[j+1] : 0.f;
            v.z = (j+2 < 18) ? ap[j+2] : 0.f;
            v.w = (j+3 < 18) ? ap[j+3] : 0.f;
        }
        *reinterpret_cast<uint2*>(IN + row*IN_STR + c4*2) =
            make_uint2(bfpack(v.x, v.y), bfpack(v.z, v.w));
    }
}

__global__ void __launch_bounds__(NTHREADS,2) ac_kernel(
    const float* __restrict__ state_one, const float* __restrict__ act_one,
    const float* __restrict__ state_others, const float* __restrict__ act_others,
    const float* __restrict__ b1, const float* __restrict__ b2,
    const float* __restrict__ be, const float* __restrict__ bv,
    const float* __restrict__ Wout, const float* __restrict__ bout,
    float* __restrict__ out, int B)
{
    extern __shared__ unsigned smu[];
    unsigned* WVPK = smu + OFF_WVPK;
    unsigned* IN   = smu + OFF_IN;
    unsigned* ACT2 = smu + OFF_ACT2;
    unsigned* X1   = smu + OFF_X1;
    float* BIA  = reinterpret_cast<float*>(smu + OFF_BIA);
    float* RED  = reinterpret_cast<float*>(smu + OFF_RED);

    const int tid = threadIdx.x;
    const int lane = tid & 31;
    const int warp = tid >> 5;
    const int g = lane >> 2, t = lane & 3;
    const int warp_m = warp & 1, warp_n = warp >> 1;
    const int b0 = blockIdx.x * BT;
    const int barid = 1 + warp_m;
    const int tid_h = ((warp >> 1) << 5) + lane;

    // ---- initial staging: Wv via cp.async; self inputs + biases ----
    for (int i = tid*4; i < 8192; i += NTHREADS*4) cp_async16(WVPK+i, g_pk+PK_WV+i);
    cp_commit();
    for (int i = tid; i < BT*20; i += NTHREADS){
        int row = i/20, c4 = i - row*20; int c = c4*4;
        float4 v;
        if (c4 < 16){
            v = *reinterpret_cast<const float4*>(state_one + (size_t)(b0+row)*64 + c);
        } else {
            const float* ap = act_one + (size_t)(b0+row)*14;
            int j = c - 64;
            v.x = (j   < 14) ? ap[j]   : 0.f;
            v.y = (j+1 < 14) ? ap[j+1] : 0.f;
            v.z = (j+2 < 14) ? ap[j+2] : 0.f;
            v.w = (j+3 < 14) ? ap[j+3] : 0.f;
        }
        *reinterpret_cast<uint2*>(IN + row*IN_STR + c4*2) =
            make_uint2(bfpack(v.x, v.y), bfpack(v.z, v.w));
    }
    for (int i = tid; i < 320; i += NTHREADS){
        float v;
        if (i < 64) v = b1[i];
        else if (i < 128) v = b2[i-64];
        else if (i < 256) v = bv[i-128];
        else v = Wout[i-256];
        BIA[i] = v;
    }
    __syncthreads();                                           // block

    // S1: x1 = relu(x @ W1 + b1) -> X1 (K=78 -> 5 ks)
    {
        float C[2][4];
        run_mma<5,2,true>(IN, IN_STR, g_pk+PK_W1, C, warp_m, warp_n, g, t, lane);
        epi_store<2,true,true>(C, X1, X1_STR, BIA, warp_m, warp_n, g, t);
    }
    BAR_HALF(barid);

    // S4: sel = x1 @ Wq_all -> fragment registers (pre-scaled)
    float sf[4][4];
    {
        float C[4][4];
        run_mma<4,4,true>(X1, X1_STR, g_pk+PK_WQ, C, warp_m, warp_n, g, t, lane);
#pragma unroll
        for (int nt=0;nt<4;nt++)
#pragma unroll
            for (int j=0;j<4;j++) sf[nt][j] = C[nt][j]*LSCALE;
    }
    // S2: x2 = relu(x1 @ W2 + b2) -> ACT2
    {
        float C[2][4];
        run_mma<4,2,true>(X1, X1_STR, g_pk+PK_W2, C, warp_m, warp_n, g, t, lane);
        epi_store<2,true,true>(C, ACT2, A2_STR, BIA+64, warp_m, warp_n, g, t);
    }
    BAR_HALF(barid);

    // S3: x3_self = x2 @ w3_self -> registers
    float x3s[2][4];
    run_mma<4,2,true>(ACT2, A2_STR, g_pk+PK_W3S, x3s, warp_m, warp_n, g, t, lane);
    // stage agent-0 inputs for this half
    stage_agent_half(IN, state_others, act_others, B, b0, 0, warp_m, tid_h);
    cp_wait0();
    __syncthreads();       // block: WVPK visible to all

    // register softmax state + ov accumulators
    float m0 = -1e30f, m1 = -1e30f, s0 = 0.f, s1 = 0.f;
    float ov[4][4];
#pragma unroll
    for (int nt=0;nt<4;nt++)
#pragma unroll
        for (int j=0;j<4;j++) ov[nt][j]=0.f;

    // ---- agent loop: 2 half-barriers per iteration ----
    for (int a = 0; a < 7; a++){
        // enc = relu(inp @ We[a] + be[a]) -> ACT2 (K=82 -> 6 ks; A zero-padded to 96)
        {
            float C[4][4];
            run_mma<6,4,true>(IN, IN_STR, g_pk+PK_WE + a*6144, C, warp_m, warp_n, g, t, lane);
            epi_store<4,true,true>(C, ACT2, A2_STR, be + a*128, warp_m, warp_n, g, t);
        }
        BAR_HALF(barid);

        if (a < 6) stage_agent_half(IN, state_others, act_others, B, b0, a+1, warp_m, tid_h);

        // keys MMA (Wk from L2) -> fragment logits -> register softmax
        float lg0, lg1;
        {
            float Ck[4][4];
            run_mma<8,4,true>(ACT2, A2_STR, g_pk+PK_WK, Ck, warp_m, warp_n, g, t, lane);
            float p0 = 0.f, p1 = 0.f;
#pragma unroll
            for (int nt=0;nt<4;nt++){
                p0 += Ck[nt][0]*sf[nt][0] + Ck[nt][1]*sf[nt][1];
                p1 += Ck[nt][2]*sf[nt][2] + Ck[nt][3]*sf[nt][3];
            }
            p0 += __shfl_xor_sync(0xffffffffu, p0, 1);
            p0 += __shfl_xor_sync(0xffffffffu, p0, 2);
            p1 += __shfl_xor_sync(0xffffffffu, p1, 1);
            p1 += __shfl_xor_sync(0xffffffffu, p1, 2);
            lg0 = p0; lg1 = p1;
        }
        float mn0 = fmaxf(m0, lg0), mn1 = fmaxf(m1, lg1);
        float al0 = __expf(m0 - mn0), al1 = __expf(m1 - mn1);
        float pv0 = __expf(lg0 - mn0), pv1 = __expf(lg1 - mn1);
        s0 = s0*al0 + pv0; s1 = s1*al1 + pv1;
        m0 = mn0; m1 = mn1;

        // vals MMA (B = resident Wv in smem) + local epilogue into ov
        {
            float Cv[4][4];
            run_mma<8,4,false>(ACT2, A2_STR, WVPK, Cv, warp_m, warp_n, g, t, lane);
#pragma unroll
            for (int nt=0;nt<4;nt++){
                int col = warp_n*32 + nt*8 + 2*t;
                float bv0 = BIA[128+col], bv1 = BIA[128+col+1];
                float v0 = fmaxf(Cv[nt][0]+bv0, 0.f);
                float v1 = fmaxf(Cv[nt][1]+bv1, 0.f);
                float v2 = fmaxf(Cv[nt][2]+bv0, 0.f);
                float v3 = fmaxf(Cv[nt][3]+bv1, 0.f);
                ov[nt][0] = ov[nt][0]*al0 + pv0*v0;
                ov[nt][1] = ov[nt][1]*al0 + pv0*v1;
                ov[nt][2] = ov[nt][2]*al1 + pv1*v2;
                ov[nt][3] = ov[nt][3]*al1 + pv1*v3;
            }
        }
        BAR_HALF(barid);
    }

    // x2_others = ov / s -> ACT2 (bf16 packed), fragment-local
    {
        int r0 = warp_m*16 + g, r1 = r0 + 8;
        float i0 = 1.f / s0, i1 = 1.f / s1;
#pragma unroll
        for (int nt=0;nt<4;nt++){
            int c2 = warp_n*16 + nt*4 + t;
            ACT2[r0*A2_STR + c2] = bfpack(ov[nt][0]*i0, ov[nt][1]*i0);
            ACT2[r1*A2_STR + c2] = bfpack(ov[nt][2]*i1, ov[nt][3]*i1);
        }
    }
    BAR_HALF(barid);

    // S8: x3o = x2o @ w3_others; x3 = relu(x3_self + x3o); dot Wout
    {
        float C[2][4];
        run_mma<8,2,true>(ACT2, A2_STR, g_pk+PK_W3O, C, warp_m, warp_n, g, t, lane);
        int r0 = warp_m*16 + g;
        float pr0 = 0.f, pr1 = 0.f;
#pragma unroll
        for (int nt=0;nt<2;nt++){
            int col = warp_n*16 + nt*8 + 2*t;
            float w0 = BIA[256+col], w1 = BIA[256+col+1];
            pr0 += fmaxf(C[nt][0]+x3s[nt][0], 0.f)*w0 + fmaxf(C[nt][1]+x3s[nt][1], 0.f)*w1;
            pr1 += fmaxf(C[nt][2]+x3s[nt][2], 0.f)*w0 + fmaxf(C[nt][3]+x3s[nt][3], 0.f)*w1;
        }
        pr0 += __shfl_xor_sync(0xffffffffu, pr0, 1);
        pr1 += __shfl_xor_sync(0xffffffffu, pr1, 1);
        pr0 += __shfl_xor_sync(0xffffffffu, pr0, 2);
        pr1 += __shfl_xor_sync(0xffffffffu, pr1, 2);
        if (t == 0){
            RED[warp_n*32 + r0]     = pr0;
            RED[warp_n*32 + r0 + 8] = pr1;
        }
    }
    __syncthreads();
    if (tid < 32){
        out[b0 + tid] = RED[tid] + RED[32+tid] + RED[64+tid] + RED[96+tid] + bout[0];
    }
}

extern "C" void kernel_launch(void* const* d_in, const int* in_sizes, int n_in,
                              void* d_out, int out_size)
{
    const float* state_one    = (const float*)d_in[0];
    const float* act_one      = (const float*)d_in[1];
    const float* state_others = (const float*)d_in[2];
    const float* act_others   = (const float*)d_in[3];
    const float* W1   = (const float*)d_in[4];
    const float* b1   = (const float*)d_in[5];
    const float* W2   = (const float*)d_in[6];
    const float* b2   = (const float*)d_in[7];
    const float* w3s  = (const float*)d_in[8];
    const float* We   = (const float*)d_in[9];
    const float* be   = (const float*)d_in[10];
    const float* Wk   = (const float*)d_in[11];
    const float* Wq   = (const float*)d_in[12];
    const float* Wv   = (const float*)d_in[13];
    const float* bv   = (const float*)d_in[14];
    const float* w3o  = (const float*)d_in[15];
    const float* Wout = (const float*)d_in[16];
    const float* bout = (const float*)d_in[17];
    float* out = (float*)d_out;

    int B = in_sizes[0] / 64;

    prep_kernel<<<138, 256>>>(W1, Wq, W2, w3s, w3o, Wk, Wv, We);

    int smem_bytes = SMEM_WORDS * 4;
    cudaFuncSetAttribute(ac_kernel, cudaFuncAttributeMaxDynamicSharedMemorySize, smem_bytes);
    ac_kernel<<<B/BT, NTHREADS, smem_bytes>>>(
        state_one, act_one, state_others, act_others,
        b1, b2, be, bv, Wout, bout, out, B);
}